// round 17
// baseline (speedup 1.0000x reference)
#include <cuda_runtime.h>
#include <cstdint>

#define NLINES 12288       // 24 planes * 512 lines
#define LW 512
#define KS 121
#define NT 32              // lines per CTA
#define MT 256             // outputs per CTA along the line
#define KSPAN 376          // k columns per CTA (256 + 120 halo)
#define PK 388             // B pitch in floats (388 mod 32 = 4 -> conflict-free frags)

// dynamic smem layout
#define SM_B 0             // B [32 n][KSPAN k] fp32(tf32), pitch PK: 49664 B
#define SM_WT 49664        // u32[176] tf32 weight table wt[i] = w[i-32] (zero-padded)
#define SM_SRED 50368      // float[128]
#define SM_TOTAL 50880     // 4 CTAs/SM = 203.5 KB

__device__ float g_tmp[NLINES * LW];

static __device__ __forceinline__ uint32_t cvt_tf32(float v) {
    uint32_t o;
    asm("cvt.rna.tf32.f32 %0, %1;" : "=r"(o) : "f"(v));
    return o;
}

static __device__ __forceinline__ void mma_tf32(float* c, uint32_t a0, uint32_t a1,
                                                uint32_t a2, uint32_t a3,
                                                uint32_t b0, uint32_t b1) {
    asm volatile(
        "mma.sync.aligned.m16n8k8.row.col.f32.tf32.tf32.f32 "
        "{%0,%1,%2,%3}, {%4,%5,%6,%7}, {%8,%9}, {%0,%1,%2,%3};"
        : "+f"(c[0]), "+f"(c[1]), "+f"(c[2]), "+f"(c[3])
        : "r"(a0), "r"(a1), "r"(a2), "r"(a3), "r"(b0), "r"(b1));
}

// ---------------------------------------------------------------------------
// Separable-blur pass as banded GEMM on tensor cores (tf32 single term).
// Warp owns TWO 16-row m-strips (m0, m0+16) sharing every B fragment; the
// Toeplitz A-fragments come from two strided weight streams E/F kept as a
// rotating register history (strip1 = strip0 delayed by 2 chunks), so only
// 2 table LDS per chunk feed 8 MMAs.  Output plane-transposed; two passes
// compose to the correct layout.
// ---------------------------------------------------------------------------
__global__ __launch_bounds__(256, 4)
void blur_pass(const float* __restrict__ x, float* __restrict__ outp,
               const float* __restrict__ sigma, int first) {
    extern __shared__ char smem[];
    int tid = threadIdx.x;
    int ib = blockIdx.x;             // 0..1: 256-output block along the line
    int L0 = blockIdx.y * NT;        // first line of the 32-line tile
    int Mb = ib * MT;

    const float* in = first ? x : (const float*)g_tmp;
    float* out = first ? (float*)g_tmp : outp;

    // ---- B build: thread owns k-columns tid and tid+256; tf32-rounded ----
    {
        int k1 = tid, k2 = tid + 256;
        int gx1 = min(max(Mb - 60 + k1, 0), LW - 1);
        int gx2 = min(max(Mb - 60 + k2, 0), LW - 1);
        const float* ip = in + (long)L0 * LW;
        uint32_t* bsw = (uint32_t*)(smem + SM_B);
        if (k2 < KSPAN) {
            #pragma unroll 4
            for (int n = 0; n < NT; n++) {
                bsw[n * PK + k1] = cvt_tf32(ip[(long)n * LW + gx1]);
                bsw[n * PK + k2] = cvt_tf32(ip[(long)n * LW + gx2]);
            }
        } else {
            #pragma unroll 4
            for (int n = 0; n < NT; n++)
                bsw[n * PK + k1] = cvt_tf32(ip[(long)n * LW + gx1]);
        }
    }

    // ---- weight table: wt[i] = tf32(w[i-32]), zeros outside [32,152] ----
    {
        float* sred = (float*)(smem + SM_SRED);
        float e = 0.0f;
        if (tid < 128) {
            float s = sigma[0] * 8.0f + 16.0f;
            float d = (float)(tid - 60);
            e = (tid < KS) ? expf(-(d * d) / (2.0f * s * s)) : 0.0f;
            sred[tid] = e;
        }
        __syncthreads();
        if (tid < 32) {
            float s4 = sred[tid] + sred[tid + 32] + sred[tid + 64] + sred[tid + 96];
            #pragma unroll
            for (int off = 16; off > 0; off >>= 1)
                s4 += __shfl_xor_sync(0xffffffffu, s4, off);
            if (tid == 0) sred[0] = s4;
        }
        __syncthreads();
        float sum = sred[0];
        uint32_t* wtw = (uint32_t*)(smem + SM_WT);
        if (tid < 32) wtw[tid] = 0u;                     // wt[0..31]
        if (tid < 128) wtw[tid + 32] = cvt_tf32(e / sum); // wt[32..159] (121..127 -> 0)
        else if (tid < 144) wtw[tid + 32] = 0u;          // wt[160..175]
    }
    __syncthreads();

    // ---- mainloop: warp = strips (32w, 32w+16); 18 k8-chunks ----
    int wid = tid >> 5, lane = tid & 31;
    int g = lane >> 2, t = lane & 3;
    int Kw = wid * 32;               // warp k-column base (= strip0 m offset)

    float c0[4][4], c1[4][4];
    #pragma unroll
    for (int j = 0; j < 4; j++)
        #pragma unroll
        for (int r = 0; r < 4; r++) { c0[j][r] = 0.0f; c1[j][r] = 0.0f; }

    const uint32_t* bs = (const uint32_t*)(smem + SM_B);
    // E(u) = Ebase[8u] = w[c+8u], F(u) = Ebase[8u+4], c = t-g
    const uint32_t* Ebase = (const uint32_t*)(smem + SM_WT) + (t - g + 32);

    uint32_t E1 = Ebase[-8],  E2 = Ebase[-16], E3 = Ebase[-24];
    uint32_t F1 = Ebase[-4],  F2 = Ebase[-12], F3 = Ebase[-20];

    #pragma unroll
    for (int u = 0; u < 18; u++) {
        uint32_t E0 = Ebase[8 * u];
        uint32_t F0 = Ebase[8 * u + 4];

        // B fragments for this chunk (shared by both strips)
        uint32_t b[4][2];
        int kb = Kw + 8 * u;
        #pragma unroll
        for (int j = 0; j < 4; j++) {
            const uint32_t* bp = bs + (8 * j + g) * PK + kb + t;
            b[j][0] = bp[0];
            b[j][1] = bp[4];
        }

        if (u <= 16) {                 // strip0: rows Kw .. Kw+15
            #pragma unroll
            for (int j = 0; j < 4; j++)
                mma_tf32(c0[j], E0, E1, F0, F1, b[j][0], b[j][1]);
        }
        if (u >= 2) {                  // strip1: rows Kw+16 .. Kw+31
            #pragma unroll
            for (int j = 0; j < 4; j++)
                mma_tf32(c1[j], E2, E3, F2, F3, b[j][0], b[j][1]);
        }

        E3 = E2; E2 = E1; E1 = E0;
        F3 = F2; F2 = F1; F1 = F0;
    }

    // ---- epilogue: D[m][n] -> plane-transposed store, both strips ----
    {
        int p = L0 >> 9;                  // plane
        int lp0 = L0 & 511;               // line within plane
        long row = (long)(p * 512 + Mb + Kw + g);
        float* o0 = out + row * 512 + lp0;
        #pragma unroll
        for (int j = 0; j < 4; j++) {
            int n = 8 * j + 2 * t;
            *(float2*)(o0 + n) = make_float2(c0[j][0], c0[j][1]);
            *(float2*)(o0 + 8 * 512 + n) = make_float2(c0[j][2], c0[j][3]);
            *(float2*)(o0 + 16 * 512 + n) = make_float2(c1[j][0], c1[j][1]);
            *(float2*)(o0 + 24 * 512 + n) = make_float2(c1[j][2], c1[j][3]);
        }
    }
}

// ---------------------------------------------------------------------------
extern "C" void kernel_launch(void* const* d_in, const int* in_sizes, int n_in,
                              void* d_out, int out_size) {
    const float* x     = (const float*)d_in[0];
    const float* sigma = (const float*)d_in[1];
    float* out = (float*)d_out;

    cudaFuncSetAttribute(blur_pass, cudaFuncAttributeMaxDynamicSharedMemorySize,
                         SM_TOTAL);

    dim3 grid(LW / MT, NLINES / NT);   // 2 x 384 = 768 CTAs
    blur_pass<<<grid, 256, SM_TOTAL>>>(x, out, sigma, 1);   // x -> g_tmp (T)
    blur_pass<<<grid, 256, SM_TOTAL>>>(x, out, sigma, 0);   // g_tmp -> out (T back)
}